// round 16
// baseline (speedup 1.0000x reference)
#include <cuda_runtime.h>
#include <cuda_bf16.h>
#include <cstdint>

#define NBATCH 512
#define HID 512
#define DDIM 9
#define TENC 257
#define TDEC 256
#define NSTEPS 513
#define NCTA 128
#define NTHREADS 512
#define XPS 68
#define DEPTH 2

// smem layout (bytes)
#define SM_BIAS 0
#define SM_WIH  256
#define SM_XP   3584
#define SM_HFH  38400
#define SM_HFM  42496
#define SM_W    47104                 // 128KB persistent packed W (1KB-aligned)
#define SMEM_BYTES (SM_W + 131072)    // 178176

typedef unsigned short ushort_t;

// fragment-packed bf16 hidden state (hi & mid terms), per time-buffer, per mb slab
__device__ __align__(16) ushort_t g_habf[2][4*65536];
__device__ __align__(16) ushort_t g_hmbf[2][4*65536];
__device__ __align__(16) float    g_hrm[2][NBATCH*HID];   // row-major fp32 for FC head
__device__ unsigned s_cnt[5*32];
__device__ unsigned s_gen[5*32];

__device__ __forceinline__ float sigf(float x){ return 1.0f/(1.0f+__expf(-x)); }
__device__ __forceinline__ float tanh_fast(float x){
    return 2.0f/(1.0f+__expf(-2.0f*x)) - 1.0f;
}
__device__ __forceinline__ ushort_t bf16u(float v){
    __nv_bfloat16 b = __float2bfloat16_rn(v);
    return *(ushort_t*)&b;
}
__device__ __forceinline__ float bf16f(ushort_t u){
    __nv_bfloat16 b = *(__nv_bfloat16*)&u;
    return __bfloat162float(b);
}
__device__ __forceinline__ void mma16(float* d, const uint4& a, uint32_t b0, uint32_t b1){
    asm volatile("mma.sync.aligned.m16n8k16.row.col.f32.bf16.bf16.f32 "
        "{%0,%1,%2,%3}, {%4,%5,%6,%7}, {%8,%9}, {%0,%1,%2,%3};"
        : "+f"(d[0]), "+f"(d[1]), "+f"(d[2]), "+f"(d[3])
        : "r"(a.x), "r"(a.y), "r"(a.z), "r"(a.w), "r"(b0), "r"(b1));
}

__device__ __forceinline__ void bar_sync(int g, unsigned count){
    __syncthreads();
    if (threadIdx.x == 0) {
        __threadfence();
        volatile unsigned* genp = &s_gen[g*32];
        unsigned target = *genp + 1u;
        if (atomicAdd(&s_cnt[g*32], 1u) == count - 1u) {
            atomicExch(&s_cnt[g*32], 0u);
            __threadfence();
            atomicExch((unsigned*)&s_gen[g*32], target);
        } else {
            while ((int)(*genp - target) < 0) { }
        }
        __threadfence();
    }
    __syncthreads();
}

// FC head on warps 8-15 (8 warps, 36 outputs)
__device__ __forceinline__ void fc_out_w8(const float* __restrict__ h,
                                          const float* __restrict__ fcW,
                                          const float* __restrict__ fcb,
                                          float* __restrict__ out,
                                          int n0, int td, int wid, int lane){
    for (int o = wid - 8; o < 4*DDIM; o += 8) {
        int rr = o / DDIM, d = o - rr*DDIM;
        int n = n0 + rr;
        const float* hr = h + (size_t)n*HID;
        const float* wr = fcW + d*HID;
        float s = 0.0f;
#pragma unroll
        for (int j = 0; j < 16; ++j)
            s += __ldcg(hr + j*32 + lane) * wr[j*32 + lane];
#pragma unroll
        for (int off = 16; off; off >>= 1)
            s += __shfl_xor_sync(0xffffffffu, s, off);
        if (lane == 0)
            out[((size_t)n*TDEC + td)*DDIM + d] = sigf(s + fcb[d]);
    }
}

__global__ void __launch_bounds__(NTHREADS, 1)
lstm_kernel(const float* __restrict__ x, const float* __restrict__ W_ih,
            const float* __restrict__ W_hh, const float* __restrict__ b_ih,
            const float* __restrict__ b_hh, const float* __restrict__ fcW,
            const float* __restrict__ fcb, const float* __restrict__ h0,
            const float* __restrict__ c0, float* __restrict__ out){
    extern __shared__ char smem[];
    float* bias = (float*)(smem + SM_BIAS);
    float* wih  = (float*)(smem + SM_WIH);
    float* xp   = (float*)(smem + SM_XP);
    ushort_t* hfh = (ushort_t*)(smem + SM_HFH);
    ushort_t* hfm = (ushort_t*)(smem + SM_HFM);
    ushort_t* wsm = (ushort_t*)(smem + SM_W);
    const uint4* wsm4 = (const uint4*)(smem + SM_W);

    const int tid = threadIdx.x, bx = blockIdx.x;
    const int mb = bx >> 5, gb = bx & 31;
    const int m0 = mb * 128;
    const int lane = tid & 31, wid = tid >> 5;
    const int wm = wid & 3, wn = (wid >> 2) & 1;   // MMA warps 0-7: rows wm*32, cols wn*32

    // ---- one-time init ----
    for (int flat = tid; flat < 64*HID; flat += NTHREADS) {
        int c = flat >> 9, k = flat & 511;
        int gr = (c & 3)*HID + gb*16 + (c >> 2);      // col c = unit*4 + gate(i,f,g,o)
        float wv = W_hh[(size_t)gr*HID + k];
        ushort_t hi = bf16u(wv);
        ushort_t mi = bf16u(wv - bf16f(hi));
        int ci = (k>>4)*256 + (c>>3)*32 + (c&7)*4 + ((k&7)>>1);
        int pos = 2*((k>>3)&1) + (k&1);
        wsm[ci*8 + pos]     = hi;
        wsm[ci*8 + 4 + pos] = mi;
    }
    for (int c = tid; c < 64; c += NTHREADS) {
        int gr = (c & 3)*HID + gb*16 + (c >> 2);
        bias[c] = b_ih[gr] + b_hh[gr];
        for (int d = 0; d < DDIM; ++d) wih[c*12 + d] = W_ih[gr*DDIM + d];
    }
    for (int idx = bx*2048 + tid; idx < (bx+1)*2048; idx += NTHREADS) {
        int r = idx >> 9, j = idx & 511;
        float v = h0[j];
        g_hrm[0][(size_t)r*HID + j] = v;
        int mbb = r >> 7, m = r & 127;
        int ci = (j>>4)*256 + (m>>4)*32 + (m&7)*4 + ((j&7)>>1);
        int pos = 2*((m>>3)&1) + 4*((j>>3)&1) + (j&1);
        ushort_t hi = bf16u(v);
        g_habf[0][mbb*65536 + ci*8 + pos] = hi;
        g_hmbf[0][mbb*65536 + ci*8 + pos] = bf16u(v - bf16f(hi));
    }
    // c-state for MMA warps: 8 cells per thread (2 mt x 4 nt), c0 broadcast over rows
    const int g = lane >> 2, tq = lane & 3;
    float c_reg[8];
#pragma unroll
    for (int nt = 0; nt < 4; ++nt) {
        float cv = c0[gb*16 + wn*8 + 2*nt + (tq >> 1)];
        c_reg[nt] = cv; c_reg[4 + nt] = cv;
    }
    bar_sync(4, NCTA);

    const int boff = wn*4*32 + lane;

    // ---- time loop ----
    for (int s = 0; s < NSTEPS; ++s) {
        const int rb = s & 1;
        const uint4* __restrict__ hsrc = (const uint4*)(g_habf[rb] + mb*65536);
        const uint4* __restrict__ msrc = (const uint4*)(g_hmbf[rb] + mb*65536);
        const bool enc = (s < TENC);

        float d[2][4][4];

        if (wid < 8) {
            // ---- GEMM: 32 k16-blocks, tile 32x32, sync-free ----
#pragma unroll
            for (int mt = 0; mt < 2; ++mt)
#pragma unroll
                for (int nt = 0; nt < 4; ++nt)
#pragma unroll
                    for (int q = 0; q < 4; ++q) d[mt][nt][q] = 0.0f;

            const int aoff0 = (wm*2 + 0)*32 + lane;
            const int aoff1 = (wm*2 + 1)*32 + lane;
            uint4 Ah[DEPTH][2], Am[DEPTH][2];
#pragma unroll
            for (int p = 0; p < DEPTH; ++p) {
                Ah[p][0] = __ldcg(hsrc + p*256 + aoff0);
                Ah[p][1] = __ldcg(hsrc + p*256 + aoff1);
                Am[p][0] = __ldcg(msrc + p*256 + aoff0);
                Am[p][1] = __ldcg(msrc + p*256 + aoff1);
            }
#pragma unroll
            for (int kb = 0; kb < 32; ++kb) {
                const int slot = kb & (DEPTH - 1);
                const uint4 A1h = Ah[slot][0], A2h = Ah[slot][1];
                const uint4 A1m = Am[slot][0], A2m = Am[slot][1];
                if (kb + DEPTH < 32) {
                    Ah[slot][0] = __ldcg(hsrc + (kb+DEPTH)*256 + aoff0);
                    Ah[slot][1] = __ldcg(hsrc + (kb+DEPTH)*256 + aoff1);
                    Am[slot][0] = __ldcg(msrc + (kb+DEPTH)*256 + aoff0);
                    Am[slot][1] = __ldcg(msrc + (kb+DEPTH)*256 + aoff1);
                }
#pragma unroll
                for (int nt = 0; nt < 4; ++nt) {
                    const uint4 B = wsm4[kb*256 + boff + nt*32];
                    mma16(d[0][nt], A1h, B.x, B.y);   // hi*hi
                    mma16(d[0][nt], A1h, B.z, B.w);   // hi*mid
                    mma16(d[0][nt], A1m, B.x, B.y);   // mid*hi
                    mma16(d[1][nt], A2h, B.x, B.y);
                    mma16(d[1][nt], A2h, B.z, B.w);
                    mma16(d[1][nt], A2m, B.x, B.y);
                }
            }
        } else {
            // ---- helper warps: decode FC output / encode x-projection ----
            if (s >= TENC + 1)
                fc_out_w8(g_hrm[rb], fcW, fcb, out, m0 + gb*4, s - (TENC+1), wid, lane);
            if (enc) {
                const int t2 = tid - 256;          // 0..255
                const int xrow = t2 >> 1, cb = (t2 & 1)*32;
                float xv[DDIM];
#pragma unroll
                for (int dd = 0; dd < DDIM; ++dd)
                    xv[dd] = __ldg(x + (size_t)(m0 + xrow)*(TENC*DDIM) + s*DDIM + dd);
                float sg[32];
#pragma unroll
                for (int c = 0; c < 32; ++c) sg[c] = bias[cb + c];
#pragma unroll
                for (int dd = 0; dd < DDIM; ++dd)
#pragma unroll
                    for (int c = 0; c < 32; ++c) sg[c] += xv[dd]*wih[(cb + c)*12 + dd];
#pragma unroll
                for (int c = 0; c < 32; c += 4)
                    *(float4*)(xp + xrow*XPS + cb + c) =
                        make_float4(sg[c], sg[c+1], sg[c+2], sg[c+3]);
            }
        }

        // ---- epilogue (MMA warps): shuffle gate quads, cell update ----
        __syncthreads();   // xp ready + staging WAR vs previous copy
        if (wid < 8) {
#pragma unroll
            for (int mt = 0; mt < 2; ++mt) {
                const int erow = wm*32 + mt*16 + g + 8*(tq & 1);
#pragma unroll
                for (int nt = 0; nt < 4; ++nt) {
                    const int u = wn*8 + 2*nt + (tq >> 1);
                    float s0 = (tq & 1) ? d[mt][nt][0] : d[mt][nt][2];
                    float s1 = (tq & 1) ? d[mt][nt][1] : d[mt][nt][3];
                    float r0 = __shfl_xor_sync(0xffffffffu, s0, 1);
                    float r1 = __shfl_xor_sync(0xffffffffu, s1, 1);
                    float iv, fv, gv, ov;
                    if ((tq & 1) == 0) { iv = d[mt][nt][0]; fv = d[mt][nt][1]; gv = r0; ov = r1; }
                    else               { iv = r0; fv = r1; gv = d[mt][nt][2]; ov = d[mt][nt][3]; }
                    float ai, af, ag, ao;
                    if (enc) {
                        float4 a = *(float4*)(xp + erow*XPS + u*4);
                        ai = a.x; af = a.y; ag = a.z; ao = a.w;
                    } else {
                        float4 b = *(float4*)(bias + u*4);
                        ai = b.x; af = b.y; ag = b.z; ao = b.w;
                    }
                    float cn = sigf(fv + af)*c_reg[mt*4 + nt]
                             + sigf(iv + ai)*tanh_fast(gv + ag);
                    c_reg[mt*4 + nt] = cn;
                    float h = sigf(ov + ao)*tanh_fast(cn);
                    g_hrm[rb ^ 1][(size_t)(m0 + erow)*HID + gb*16 + u] = h;
                    int ci = (erow>>4)*32 + (erow&7)*4 + ((u&7)>>1);
                    int pos = 2*((erow>>3)&1) + 4*((u>>3)&1) + (u&1);
                    ushort_t hi = bf16u(h);
                    hfh[ci*8 + pos] = hi;
                    hfm[ci*8 + pos] = bf16u(h - bf16f(hi));
                }
            }
        }
        __syncthreads();
        // linear copy staging -> global fragment-packed h (all threads)
        if (tid < 256)
            ((uint4*)(g_habf[rb ^ 1] + mb*65536))[gb*256 + tid] = ((const uint4*)hfh)[tid];
        else
            ((uint4*)(g_hmbf[rb ^ 1] + mb*65536))[gb*256 + tid - 256] = ((const uint4*)hfm)[tid - 256];
        bar_sync(mb, 32);
    }

    if (wid >= 8)
        fc_out_w8(g_hrm[NSTEPS & 1], fcW, fcb, out, m0 + gb*4, TDEC - 1, wid, lane);
}

extern "C" void kernel_launch(void* const* d_in, const int* in_sizes, int n_in,
                              void* d_out, int out_size){
    (void)in_sizes; (void)n_in; (void)out_size;
    cudaFuncSetAttribute(lstm_kernel, cudaFuncAttributeMaxDynamicSharedMemorySize,
                         SMEM_BYTES);
    lstm_kernel<<<NCTA, NTHREADS, SMEM_BYTES>>>(
        (const float*)d_in[0], (const float*)d_in[1], (const float*)d_in[2],
        (const float*)d_in[3], (const float*)d_in[4], (const float*)d_in[5],
        (const float*)d_in[6], (const float*)d_in[7], (const float*)d_in[8],
        (float*)d_out);
}

// round 17
// speedup vs baseline: 1.1683x; 1.1683x over previous
#include <cuda_runtime.h>
#include <cuda_bf16.h>
#include <cstdint>

#define NBATCH 512
#define HID 512
#define DDIM 9
#define TENC 257
#define TDEC 256
#define NSTEPS 513
#define NCTA 256
#define NTHREADS 256
#define XPS 36
#define DEPTH 4

// smem layout (bytes)
#define SM_BIAS 0
#define SM_WIH  128
#define SM_XP   1664
#define SM_HFH  20096
#define SM_HFM  22144
#define SM_W    24576                 // 64KB persistent packed W (1KB-aligned)
#define SMEM_BYTES (SM_W + 65536)     // 90112

typedef unsigned short ushort_t;

// fragment-packed bf16 hidden state (hi & mid terms), per time-buffer, per mb slab
__device__ __align__(16) ushort_t g_habf[2][4*65536];
__device__ __align__(16) ushort_t g_hmbf[2][4*65536];
__device__ __align__(16) float    g_hrm[2][NBATCH*HID];   // row-major fp32 for FC head
__device__ unsigned s_cnt[5*32];
__device__ unsigned s_gen[5*32];

__device__ __forceinline__ float sigf(float x){ return 1.0f/(1.0f+__expf(-x)); }
__device__ __forceinline__ float tanh_fast(float x){
    return 2.0f/(1.0f+__expf(-2.0f*x)) - 1.0f;
}
__device__ __forceinline__ ushort_t bf16u(float v){
    __nv_bfloat16 b = __float2bfloat16_rn(v);
    return *(ushort_t*)&b;
}
__device__ __forceinline__ float bf16f(ushort_t u){
    __nv_bfloat16 b = *(__nv_bfloat16*)&u;
    return __bfloat162float(b);
}
__device__ __forceinline__ void mma16(float* d, const uint4& a, uint32_t b0, uint32_t b1){
    asm volatile("mma.sync.aligned.m16n8k16.row.col.f32.bf16.bf16.f32 "
        "{%0,%1,%2,%3}, {%4,%5,%6,%7}, {%8,%9}, {%0,%1,%2,%3};"
        : "+f"(d[0]), "+f"(d[1]), "+f"(d[2]), "+f"(d[3])
        : "r"(a.x), "r"(a.y), "r"(a.z), "r"(a.w), "r"(b0), "r"(b1));
}

// barrier over the 64 CTAs of one mb group
__device__ __forceinline__ void bar_sync(int g, unsigned count){
    __syncthreads();
    if (threadIdx.x == 0) {
        __threadfence();
        volatile unsigned* genp = &s_gen[g*32];
        unsigned target = *genp + 1u;
        if (atomicAdd(&s_cnt[g*32], 1u) == count - 1u) {
            atomicExch(&s_cnt[g*32], 0u);
            __threadfence();
            atomicExch((unsigned*)&s_gen[g*32], target);
        } else {
            while ((int)(*genp - target) < 0) { }
        }
        __threadfence();
    }
    __syncthreads();
}

// FC head: 2 rows x 9 outputs per CTA across 8 warps
__device__ __forceinline__ void fc_out(const float* __restrict__ h,
                                       const float* __restrict__ fcW,
                                       const float* __restrict__ fcb,
                                       float* __restrict__ out,
                                       int n0, int td, int wid, int lane){
    for (int o = wid; o < 2*DDIM; o += 8) {
        int rr = o / DDIM, d = o - rr*DDIM;
        int n = n0 + rr;
        const float* hr = h + (size_t)n*HID;
        const float* wr = fcW + d*HID;
        float s = 0.0f;
#pragma unroll
        for (int j = 0; j < 16; ++j)
            s += __ldcg(hr + j*32 + lane) * wr[j*32 + lane];
#pragma unroll
        for (int off = 16; off; off >>= 1)
            s += __shfl_xor_sync(0xffffffffu, s, off);
        if (lane == 0)
            out[((size_t)n*TDEC + td)*DDIM + d] = sigf(s + fcb[d]);
    }
}

__global__ void __launch_bounds__(NTHREADS, 2)
lstm_kernel(const float* __restrict__ x, const float* __restrict__ W_ih,
            const float* __restrict__ W_hh, const float* __restrict__ b_ih,
            const float* __restrict__ b_hh, const float* __restrict__ fcW,
            const float* __restrict__ fcb, const float* __restrict__ h0,
            const float* __restrict__ c0, float* __restrict__ out){
    extern __shared__ char smem[];
    float* bias = (float*)(smem + SM_BIAS);
    float* wih  = (float*)(smem + SM_WIH);
    float* xp   = (float*)(smem + SM_XP);
    ushort_t* hfh = (ushort_t*)(smem + SM_HFH);
    ushort_t* hfm = (ushort_t*)(smem + SM_HFM);
    ushort_t* wsm = (ushort_t*)(smem + SM_W);
    const uint4* wsm4 = (const uint4*)(smem + SM_W);

    const int tid = threadIdx.x, bx = blockIdx.x;
    const int mb = bx >> 6, gb = bx & 63;        // 4 mb groups x 64 gate blocks (8 units)
    const int m0 = mb * 128;
    const int lane = tid & 31, wid = tid >> 5;
    const int wm = wid;                           // warp tile: rows wm*16, all 32 cols

    // ---- one-time init ----
    // W split bf16 hi/mid, fragment-packed into persistent smem (32 gate cols)
    for (int flat = tid; flat < 32*HID; flat += NTHREADS) {
        int c = flat >> 9, k = flat & 511;
        int gr = (c & 3)*HID + gb*8 + (c >> 2);     // col c = unit*4 + gate(i,f,g,o)
        float wv = W_hh[(size_t)gr*HID + k];
        ushort_t hi = bf16u(wv);
        ushort_t mi = bf16u(wv - bf16f(hi));
        int ci = (k>>4)*128 + (c>>3)*32 + (c&7)*4 + ((k&7)>>1);
        int pos = 2*((k>>3)&1) + (k&1);
        wsm[ci*8 + pos]     = hi;
        wsm[ci*8 + 4 + pos] = mi;
    }
    for (int c = tid; c < 32; c += NTHREADS) {
        int gr = (c & 3)*HID + gb*8 + (c >> 2);
        bias[c] = b_ih[gr] + b_hh[gr];
        for (int d = 0; d < DDIM; ++d) wih[c*12 + d] = W_ih[gr*DDIM + d];
    }
    for (int idx = bx*1024 + tid; idx < (bx+1)*1024; idx += NTHREADS) {
        int r = idx >> 9, j = idx & 511;
        float v = h0[j];
        g_hrm[0][(size_t)r*HID + j] = v;
        int mbb = r >> 7, m = r & 127;
        int ci = (j>>4)*256 + (m>>4)*32 + (m&7)*4 + ((j&7)>>1);
        int pos = 2*((m>>3)&1) + 4*((j>>3)&1) + (j&1);
        ushort_t hi = bf16u(v);
        g_habf[0][mbb*65536 + ci*8 + pos] = hi;
        g_hmbf[0][mbb*65536 + ci*8 + pos] = bf16u(v - bf16f(hi));
    }
    // c-state: 4 cells per thread matching fragment layout
    const int g = lane >> 2, tq = lane & 3;
    float c_reg[4];
#pragma unroll
    for (int nt = 0; nt < 4; ++nt)
        c_reg[nt] = c0[gb*8 + 2*nt + (tq >> 1)];
    bar_sync(4, NCTA);

    const int aoff = wm*32 + lane;

    // ---- time loop ----
    for (int s = 0; s < NSTEPS; ++s) {
        const int rb = s & 1;
        const uint4* __restrict__ hsrc = (const uint4*)(g_habf[rb] + mb*65536);
        const uint4* __restrict__ msrc = (const uint4*)(g_hmbf[rb] + mb*65536);
        const bool enc = (s < TENC);

        float d[4][4];
#pragma unroll
        for (int nt = 0; nt < 4; ++nt)
#pragma unroll
            for (int q = 0; q < 4; ++q) d[nt][q] = 0.0f;

        // A pipeline prologue
        uint4 Ah[DEPTH], Am[DEPTH];
#pragma unroll
        for (int p = 0; p < DEPTH; ++p) {
            Ah[p] = __ldcg(hsrc + p*256 + aoff);
            Am[p] = __ldcg(msrc + p*256 + aoff);
        }

        if (s >= TENC + 1)   // decode output for previous step (2 rows per CTA)
            fc_out(g_hrm[rb], fcW, fcb, out, m0 + gb*2, s - (TENC+1), wid, lane);

        if (enc) {   // x-projection + bias -> xp[row][32]
            const int xrow = tid >> 1, cb = (tid & 1)*16;
            float xv[DDIM];
#pragma unroll
            for (int dd = 0; dd < DDIM; ++dd)
                xv[dd] = __ldg(x + (size_t)(m0 + xrow)*(TENC*DDIM) + s*DDIM + dd);
            float sg[16];
#pragma unroll
            for (int c = 0; c < 16; ++c) sg[c] = bias[cb + c];
#pragma unroll
            for (int dd = 0; dd < DDIM; ++dd)
#pragma unroll
                for (int c = 0; c < 16; ++c) sg[c] += xv[dd]*wih[(cb + c)*12 + dd];
#pragma unroll
            for (int c = 0; c < 16; c += 4)
                *(float4*)(xp + xrow*XPS + cb + c) =
                    make_float4(sg[c], sg[c+1], sg[c+2], sg[c+3]);
        }

        // ---- GEMM: 32 k16-blocks, tile 16x32, sync-free ----
#pragma unroll
        for (int kb = 0; kb < 32; ++kb) {
            const int slot = kb & (DEPTH - 1);
            const uint4 A1 = Ah[slot], A2 = Am[slot];
            if (kb + DEPTH < 32) {
                Ah[slot] = __ldcg(hsrc + (kb+DEPTH)*256 + aoff);
                Am[slot] = __ldcg(msrc + (kb+DEPTH)*256 + aoff);
            }
#pragma unroll
            for (int nt = 0; nt < 4; ++nt) {
                const uint4 B = wsm4[kb*128 + nt*32 + lane];
                mma16(d[nt], A1, B.x, B.y);   // hi*hi
                mma16(d[nt], A1, B.z, B.w);   // hi*mid
                mma16(d[nt], A2, B.x, B.y);   // mid*hi
            }
        }

        // ---- epilogue: shuffle gate quads, cell update ----
        __syncthreads();   // xp ready + staging WAR vs previous copy
        const int erow = wm*16 + g + 8*(tq & 1);
#pragma unroll
        for (int nt = 0; nt < 4; ++nt) {
            const int u = 2*nt + (tq >> 1);        // local unit 0..7
            float s0 = (tq & 1) ? d[nt][0] : d[nt][2];
            float s1 = (tq & 1) ? d[nt][1] : d[nt][3];
            float r0 = __shfl_xor_sync(0xffffffffu, s0, 1);
            float r1 = __shfl_xor_sync(0xffffffffu, s1, 1);
            float iv, fv, gv, ov;
            if ((tq & 1) == 0) { iv = d[nt][0]; fv = d[nt][1]; gv = r0; ov = r1; }
            else               { iv = r0;       fv = r1;       gv = d[nt][2]; ov = d[nt][3]; }
            float ai, af, ag, ao;
            if (enc) {
                float4 a = *(float4*)(xp + erow*XPS + u*4);
                ai = a.x; af = a.y; ag = a.z; ao = a.w;
            } else {
                float4 b = *(float4*)(bias + u*4);
                ai = b.x; af = b.y; ag = b.z; ao = b.w;
            }
            float cn = sigf(fv + af)*c_reg[nt] + sigf(iv + ai)*tanh_fast(gv + ag);
            c_reg[nt] = cn;
            float h = sigf(ov + ao)*tanh_fast(cn);
            g_hrm[rb ^ 1][(size_t)(m0 + erow)*HID + gb*8 + u] = h;
            int ci = (erow>>4)*32 + (erow&7)*4 + (u>>1);
            int pos = 2*((erow>>3)&1) + (u&1);
            ushort_t hi = bf16u(h);
            hfh[ci*4 + pos] = hi;
            hfm[ci*4 + pos] = bf16u(h - bf16f(hi));
        }
        __syncthreads();
        // copy staging -> global fragment-packed h (uint2 = half of each ci slot)
        {
            uint2* dh = (uint2*)(g_habf[rb ^ 1] + mb*65536);
            uint2* dm = (uint2*)(g_hmbf[rb ^ 1] + mb*65536);
            const int dsti = (gb >> 1)*512 + tid*2 + (gb & 1);
            dh[dsti] = ((const uint2*)hfh)[tid];
            dm[dsti] = ((const uint2*)hfm)[tid];
        }
        bar_sync(mb, 64);
    }

    fc_out(g_hrm[NSTEPS & 1], fcW, fcb, out, m0 + gb*2, TDEC - 1, wid, lane);
}

extern "C" void kernel_launch(void* const* d_in, const int* in_sizes, int n_in,
                              void* d_out, int out_size){
    (void)in_sizes; (void)n_in; (void)out_size;
    cudaFuncSetAttribute(lstm_kernel, cudaFuncAttributeMaxDynamicSharedMemorySize,
                         SMEM_BYTES);
    lstm_kernel<<<NCTA, NTHREADS, SMEM_BYTES>>>(
        (const float*)d_in[0], (const float*)d_in[1], (const float*)d_in[2],
        (const float*)d_in[3], (const float*)d_in[4], (const float*)d_in[5],
        (const float*)d_in[6], (const float*)d_in[7], (const float*)d_in[8],
        (float*)d_out);
}